// round 14
// baseline (speedup 1.0000x reference)
#include <cuda_runtime.h>

// out[j]     = dot(X[r1(j)], p), r1(j) = inds1[2j]*28 + inds1[2j+1], j in [0,100)
// out[100+j] = dot(Y[r2(j)], p)
// R12's resident shape (512 thr, launch_bounds(512,2) -> 2 CTAs/SM, 64-reg cap)
// x half-row grain: 400 independent CTAs. 296 resident at t=0, 104 work-steal
// in as slots free -> per-SM work <= 1.5 rows (vs 2.0 at grid=200). Co-resident
// CTAs overlap each other's load latency / reduce tails (unlike the serialized
// persistent loop of R13). Spread per-dot counters combine the 2 halves.

#define Q      32768
#define QV     (Q / 4)       // 8192 float4 per row
#define NSEG   2
#define SEGF4  (QV / NSEG)   // 4096 float4 per half row
#define NT     512
#define W_DIM  28
#define NDOTS  200
#define NBLK   (NDOTS * NSEG)  // 400

__device__ float        g_partial[NBLK];
__device__ unsigned int g_cnt[NDOTS];   // zero-init; finisher resets each launch

__device__ __forceinline__ float dot4(float4 a, float4 b) {
    return a.x * b.x + a.y * b.y + a.z * b.z + a.w * b.w;
}

__global__ __launch_bounds__(NT, 2)
void halfrow_dot_kernel(const float* __restrict__ X,
                        const float* __restrict__ Y,
                        const float* __restrict__ p,
                        const int*   __restrict__ inds1,
                        const int*   __restrict__ inds2,
                        float* __restrict__ out)
{
    const int b   = blockIdx.x;        // 0..399
    const int j   = b >> 1;            // dot 0..199
    const int seg = b & 1;

    const bool second = (j >= 100);
    const int jj = second ? (j - 100) : j;
    const int* __restrict__ inds = second ? inds2 : inds1;
    const float* __restrict__ M  = second ? Y : X;

    const int r = inds[2 * jj] * W_DIM + inds[2 * jj + 1];

    const float4* __restrict__ row = reinterpret_cast<const float4*>(M + (size_t)r * Q);
    const float4* __restrict__ pv  = reinterpret_cast<const float4*>(p);

    const int t = threadIdx.x;
    float sum = 0.0f;

    // 8 float4 of row + 8 of p per thread: two batches of 8 independent LDG.128
    // (same register discipline R12 proved fits in 64 regs at 2 CTAs/SM).
    #pragma unroll
    for (int batch = 0; batch < 2; batch++) {
        const int i = seg * SEGF4 + t + batch * 4 * NT;
        float4 p0 = pv[i];
        float4 p1 = pv[i +     NT];
        float4 p2 = pv[i + 2 * NT];
        float4 p3 = pv[i + 3 * NT];
        float4 a0 = row[i];
        float4 a1 = row[i +     NT];
        float4 a2 = row[i + 2 * NT];
        float4 a3 = row[i + 3 * NT];
        sum += dot4(a0, p0);
        sum += dot4(a1, p1);
        sum += dot4(a2, p2);
        sum += dot4(a3, p3);
    }

    // warp reduce
    #pragma unroll
    for (int off = 16; off > 0; off >>= 1)
        sum += __shfl_xor_sync(0xFFFFFFFFu, sum, off);

    __shared__ float warp_sums[NT / 32];
    const int lane = t & 31;
    const int wid  = t >> 5;
    if (lane == 0) warp_sums[wid] = sum;
    __syncthreads();

    if (threadIdx.x == 0) {
        float s = warp_sums[0];
        #pragma unroll
        for (int w = 1; w < NT / 32; w++) s += warp_sums[w];

        g_partial[b] = s;
        __threadfence();                            // publish partial
        unsigned int tk = atomicAdd(&g_cnt[j], 1u); // 200 spread counters
        if (tk == NSEG - 1) {
            __threadfence();                        // acquire peer partial
            const volatile float* gp = g_partial + j * NSEG;
            out[j] = gp[0] + gp[1];                 // fixed order -> deterministic
            g_cnt[j] = 0;                           // reset for next graph replay
        }
    }
}

extern "C" void kernel_launch(void* const* d_in, const int* in_sizes, int n_in,
                              void* d_out, int out_size)
{
    const float* X   = (const float*)d_in[0];
    const float* Y   = (const float*)d_in[1];
    const float* p   = (const float*)d_in[2];
    const int* inds1 = (const int*)d_in[3];
    const int* inds2 = (const int*)d_in[4];
    float* out       = (float*)d_out;

    halfrow_dot_kernel<<<NBLK, NT>>>(X, Y, p, inds1, inds2, out);
}

// round 15
// speedup vs baseline: 1.4659x; 1.4659x over previous
#include <cuda_runtime.h>
#include <cstdint>

// out[j]     = dot(X[r1(j)], p), r1(j) = inds1[2j]*28 + inds1[2j+1], j in [0,100)
// out[100+j] = dot(Y[r2(j)], p)
// 400 CTAs x 256 thr, launch_bounds(256,4) -> 64-reg cap, 4 CTAs/SM slots:
// ALL 400 half-row CTAs resident at t=0 ({2,3}/SM balanced), no waves.
// Cluster(2): blocks (2j,2j+1) are the two halves of dot j. Rank1 ships its
// block-sum to rank0's SMEM via DSMEM (mapa + st.shared::cluster), cluster
// barrier (release/acquire), rank0 adds in fixed order and writes out[j].
// No gpu-scope fence, no L2 atomics (those poisoned R3/5/7/11/13/14).

#define Q      32768
#define QV     (Q / 4)       // 8192 float4 per row
#define NSEG   2
#define SEGF4  (QV / NSEG)   // 4096 float4 per half row
#define NT     256
#define W_DIM  28
#define NDOTS  200
#define NBLK   (NDOTS * NSEG)  // 400

__device__ __forceinline__ float dot4(float4 a, float4 b) {
    return a.x * b.x + a.y * b.y + a.z * b.z + a.w * b.w;
}

__device__ __forceinline__ uint32_t smem_u32(const void* ptr) {
    uint32_t addr;
    asm("{ .reg .u64 t; cvta.to.shared.u64 t, %1; cvt.u32.u64 %0, t; }"
        : "=r"(addr) : "l"(ptr));
    return addr;
}

__global__ __launch_bounds__(NT, 4) __cluster_dims__(2, 1, 1)
void cluster_dot_kernel(const float* __restrict__ X,
                        const float* __restrict__ Y,
                        const float* __restrict__ p,
                        const int*   __restrict__ inds1,
                        const int*   __restrict__ inds2,
                        float* __restrict__ out)
{
    const int b   = blockIdx.x;        // 0..399
    const int j   = b >> 1;            // dot 0..199
    const int seg = b & 1;             // == cluster rank (contiguous pairs)

    const bool second = (j >= 100);
    const int jj = second ? (j - 100) : j;
    const int* __restrict__ inds = second ? inds2 : inds1;
    const float* __restrict__ M  = second ? Y : X;

    const int r = inds[2 * jj] * W_DIM + inds[2 * jj + 1];

    const float4* __restrict__ row = reinterpret_cast<const float4*>(M + (size_t)r * Q);
    const float4* __restrict__ pv  = reinterpret_cast<const float4*>(p);

    const int t  = threadIdx.x;
    const int i0 = seg * SEGF4 + t;
    float sum = 0.0f;

    // 16 row-f4 + 16 p-f4 per thread: 4 batches of 8 independent LDG.128
    // (32 data regs in flight -- the 64-reg discipline R12 validated).
    #pragma unroll
    for (int batch = 0; batch < 4; batch++) {
        const int i = i0 + batch * 4 * NT;
        float4 p0 = pv[i];
        float4 p1 = pv[i +     NT];
        float4 p2 = pv[i + 2 * NT];
        float4 p3 = pv[i + 3 * NT];
        float4 a0 = row[i];
        float4 a1 = row[i +     NT];
        float4 a2 = row[i + 2 * NT];
        float4 a3 = row[i + 3 * NT];
        sum += dot4(a0, p0);
        sum += dot4(a1, p1);
        sum += dot4(a2, p2);
        sum += dot4(a3, p3);
    }

    // warp reduce
    #pragma unroll
    for (int off = 16; off > 0; off >>= 1)
        sum += __shfl_xor_sync(0xFFFFFFFFu, sum, off);

    __shared__ float warp_sums[NT / 32];
    __shared__ float slot[2];          // rank0's combine slots
    const int lane = t & 31;
    const int wid  = t >> 5;
    if (lane == 0) warp_sums[wid] = sum;
    __syncthreads();

    if (t == 0) {
        float s = warp_sums[0];
        #pragma unroll
        for (int w = 1; w < NT / 32; w++) s += warp_sums[w];

        if (seg == 0) {
            slot[0] = s;               // local
        } else {
            // store into rank0's slot[1] at the same smem offset
            uint32_t local = smem_u32(&slot[1]);
            uint32_t remote;
            asm volatile("mapa.shared::cluster.u32 %0, %1, 0;"
                         : "=r"(remote) : "r"(local));
            asm volatile("st.shared::cluster.f32 [%0], %1;"
                         :: "r"(remote), "f"(s) : "memory");
        }
    }

    // cluster barrier: arrive=release / wait=acquire orders the DSMEM store
    asm volatile("barrier.cluster.arrive.aligned;" ::: "memory");
    asm volatile("barrier.cluster.wait.aligned;"   ::: "memory");

    if (seg == 0 && t == 0)
        out[j] = slot[0] + slot[1];    // fixed order -> deterministic
}

extern "C" void kernel_launch(void* const* d_in, const int* in_sizes, int n_in,
                              void* d_out, int out_size)
{
    const float* X   = (const float*)d_in[0];
    const float* Y   = (const float*)d_in[1];
    const float* p   = (const float*)d_in[2];
    const int* inds1 = (const int*)d_in[3];
    const int* inds2 = (const int*)d_in[4];
    float* out       = (float*)d_out;

    cluster_dot_kernel<<<NBLK, NT>>>(X, Y, p, inds1, inds2, out);
}

// round 16
// speedup vs baseline: 1.5037x; 1.0257x over previous
#include <cuda_runtime.h>
#include <cstdint>

// out[j]     = dot(X[r1(j)], p), r1(j) = inds1[2j]*28 + inds1[2j+1], j in [0,100)
// out[100+j] = dot(Y[r2(j)], p)
// Pair + split + cluster combine: CTA (2j+seg) computes segment `seg` of BOTH
// the X-dot j and Y-dot j, sharing its p-segment loads between them
// -> L2 traffic 51MB -> 38.4MB. 200 CTAs x 512 thr, launch_bounds(512,2)
// (2 CTAs/SM). Cluster(2): rank1 ships its two partials to rank0 via DSMEM,
// cluster barrier, rank0 writes out[j] and out[j+100] in fixed order.

#define Q      32768
#define QV     (Q / 4)       // 8192 float4 per row
#define NSEG   2
#define SEGF4  (QV / NSEG)   // 4096 float4 per half row
#define NT     512
#define W_DIM  28
#define NPAIR  100
#define NBLK   (NPAIR * NSEG)  // 200

__device__ __forceinline__ float dot4(float4 a, float4 b) {
    return a.x * b.x + a.y * b.y + a.z * b.z + a.w * b.w;
}

__device__ __forceinline__ uint32_t smem_u32(const void* ptr) {
    uint32_t addr;
    asm("{ .reg .u64 t; cvta.to.shared.u64 t, %1; cvt.u32.u64 %0, t; }"
        : "=r"(addr) : "l"(ptr));
    return addr;
}

__global__ __launch_bounds__(NT, 2) __cluster_dims__(2, 1, 1)
void pairsplit_dot_kernel(const float* __restrict__ X,
                          const float* __restrict__ Y,
                          const float* __restrict__ p,
                          const int*   __restrict__ inds1,
                          const int*   __restrict__ inds2,
                          float* __restrict__ out)
{
    const int b   = blockIdx.x;        // 0..199
    const int j   = b >> 1;            // pair 0..99
    const int seg = b & 1;             // cluster rank

    const int r1 = inds1[2 * j] * W_DIM + inds1[2 * j + 1];
    const int r2 = inds2[2 * j] * W_DIM + inds2[2 * j + 1];

    const float4* __restrict__ rowX = reinterpret_cast<const float4*>(X + (size_t)r1 * Q);
    const float4* __restrict__ rowY = reinterpret_cast<const float4*>(Y + (size_t)r2 * Q);
    const float4* __restrict__ pv   = reinterpret_cast<const float4*>(p);

    const int t  = threadIdx.x;
    const int i0 = seg * SEGF4 + t;

    float sumX = 0.0f, sumY = 0.0f;

    // 8 f4 each of p/X/Y per thread: 4 batches of 6 independent LDG.128
    // (2 p + 2 x + 2 y = 24 data regs per batch; fits the 64-reg budget).
    #pragma unroll
    for (int batch = 0; batch < 4; batch++) {
        const int i = i0 + batch * 2 * NT;
        float4 p0 = pv  [i];
        float4 p1 = pv  [i + NT];
        float4 x0 = rowX[i];
        float4 x1 = rowX[i + NT];
        float4 y0 = rowY[i];
        float4 y1 = rowY[i + NT];
        sumX += dot4(x0, p0);
        sumX += dot4(x1, p1);
        sumY += dot4(y0, p0);
        sumY += dot4(y1, p1);
    }

    // warp reduce both
    #pragma unroll
    for (int off = 16; off > 0; off >>= 1) {
        sumX += __shfl_xor_sync(0xFFFFFFFFu, sumX, off);
        sumY += __shfl_xor_sync(0xFFFFFFFFu, sumY, off);
    }

    __shared__ float warp_sums[NT / 32][2];
    __shared__ float slot[4];          // rank0: [x0, y0, x1, y1]
    const int lane = t & 31;
    const int wid  = t >> 5;
    if (lane == 0) {
        warp_sums[wid][0] = sumX;
        warp_sums[wid][1] = sumY;
    }
    __syncthreads();

    if (t == 0) {
        float sx = warp_sums[0][0];
        float sy = warp_sums[0][1];
        #pragma unroll
        for (int w = 1; w < NT / 32; w++) {
            sx += warp_sums[w][0];
            sy += warp_sums[w][1];
        }

        if (seg == 0) {
            slot[0] = sx;
            slot[1] = sy;
        } else {
            // ship both partials into rank0's slot[2], slot[3]
            uint32_t local2 = smem_u32(&slot[2]);
            uint32_t remote2;
            asm volatile("mapa.shared::cluster.u32 %0, %1, 0;"
                         : "=r"(remote2) : "r"(local2));
            asm volatile("st.shared::cluster.f32 [%0], %1;"
                         :: "r"(remote2), "f"(sx) : "memory");
            asm volatile("st.shared::cluster.f32 [%0], %1;"
                         :: "r"(remote2 + 4), "f"(sy) : "memory");
        }
    }

    // cluster barrier orders the DSMEM stores (arrive=release, wait=acquire)
    asm volatile("barrier.cluster.arrive.aligned;" ::: "memory");
    asm volatile("barrier.cluster.wait.aligned;"   ::: "memory");

    if (seg == 0 && t == 0) {
        out[j]       = slot[0] + slot[2];   // fixed order -> deterministic
        out[j + 100] = slot[1] + slot[3];
    }
}

extern "C" void kernel_launch(void* const* d_in, const int* in_sizes, int n_in,
                              void* d_out, int out_size)
{
    const float* X   = (const float*)d_in[0];
    const float* Y   = (const float*)d_in[1];
    const float* p   = (const float*)d_in[2];
    const int* inds1 = (const int*)d_in[3];
    const int* inds2 = (const int*)d_in[4];
    float* out       = (float*)d_out;

    pairsplit_dot_kernel<<<NBLK, NT>>>(X, Y, p, inds1, inds2, out);
}

// round 17
// speedup vs baseline: 1.5092x; 1.0037x over previous
#include <cuda_runtime.h>
#include <cstdint>

// out[j]     = dot(X[r1(j)], p), r1(j) = inds1[2j]*28 + inds1[2j+1], j in [0,100)
// out[100+j] = dot(Y[r2(j)], p)
// Quad + quarter-split + cluster(4) combine: quad q = dots {2q,2q+1} of X and
// {2q,2q+1} of Y share ONE read of p (L2 traffic 38.4MB -> 32MB). 50 quads x 4
// quarter-row segments = 200 CTAs x 512 thr (launch_bounds(512,2), 2 CTAs/SM).
// Ranks 1-3 ship their 4 partials to rank0 via DSMEM; one cluster barrier;
// rank0 sums in fixed (rank-major) order and writes the 4 outputs.

#define Q      32768
#define QV     (Q / 4)       // 8192 float4 per row
#define NSEG   4
#define SEGF4  (QV / NSEG)   // 2048 float4 per quarter row
#define NT     512
#define W_DIM  28
#define NQUAD  50
#define NBLK   (NQUAD * NSEG)  // 200

__device__ __forceinline__ float dot4(float4 a, float4 b) {
    return a.x * b.x + a.y * b.y + a.z * b.z + a.w * b.w;
}

__device__ __forceinline__ uint32_t smem_u32(const void* ptr) {
    uint32_t addr;
    asm("{ .reg .u64 t; cvta.to.shared.u64 t, %1; cvt.u32.u64 %0, t; }"
        : "=r"(addr) : "l"(ptr));
    return addr;
}

__global__ __launch_bounds__(NT, 2) __cluster_dims__(NSEG, 1, 1)
void quad_dot_kernel(const float* __restrict__ X,
                     const float* __restrict__ Y,
                     const float* __restrict__ p,
                     const int*   __restrict__ inds1,
                     const int*   __restrict__ inds2,
                     float* __restrict__ out)
{
    const int b   = blockIdx.x;          // 0..199
    const int q   = b >> 2;              // quad 0..49
    const int seg = b & (NSEG - 1);      // cluster rank 0..3

    const int j0 = 2 * q;                // dots j0, j0+1 of each matrix

    // 4 row pointers: X[j0], X[j0+1], Y[j0], Y[j0+1]
    const int rX0 = inds1[2 * j0]     * W_DIM + inds1[2 * j0 + 1];
    const int rX1 = inds1[2 * j0 + 2] * W_DIM + inds1[2 * j0 + 3];
    const int rY0 = inds2[2 * j0]     * W_DIM + inds2[2 * j0 + 1];
    const int rY1 = inds2[2 * j0 + 2] * W_DIM + inds2[2 * j0 + 3];

    const float4* __restrict__ row0 = reinterpret_cast<const float4*>(X + (size_t)rX0 * Q);
    const float4* __restrict__ row1 = reinterpret_cast<const float4*>(X + (size_t)rX1 * Q);
    const float4* __restrict__ row2 = reinterpret_cast<const float4*>(Y + (size_t)rY0 * Q);
    const float4* __restrict__ row3 = reinterpret_cast<const float4*>(Y + (size_t)rY1 * Q);
    const float4* __restrict__ pv   = reinterpret_cast<const float4*>(p);

    const int t  = threadIdx.x;
    const int i0 = seg * SEGF4 + t;      // 2048 f4 / 512 thr = 4 per thread

    float s0 = 0.0f, s1 = 0.0f, s2 = 0.0f, s3 = 0.0f;

    // 4 batches of 5 independent LDG.128 (1 p + 4 rows; 20 data regs in flight)
    #pragma unroll
    for (int batch = 0; batch < 4; batch++) {
        const int i = i0 + batch * NT;
        float4 pb = pv  [i];
        float4 a0 = row0[i];
        float4 a1 = row1[i];
        float4 a2 = row2[i];
        float4 a3 = row3[i];
        s0 += dot4(a0, pb);
        s1 += dot4(a1, pb);
        s2 += dot4(a2, pb);
        s3 += dot4(a3, pb);
    }

    // warp reduce all four
    #pragma unroll
    for (int off = 16; off > 0; off >>= 1) {
        s0 += __shfl_xor_sync(0xFFFFFFFFu, s0, off);
        s1 += __shfl_xor_sync(0xFFFFFFFFu, s1, off);
        s2 += __shfl_xor_sync(0xFFFFFFFFu, s2, off);
        s3 += __shfl_xor_sync(0xFFFFFFFFu, s3, off);
    }

    __shared__ float warp_sums[NT / 32][4];
    __shared__ float slot[NSEG * 4];     // rank-major: slot[rank*4 + k]
    const int lane = t & 31;
    const int wid  = t >> 5;
    if (lane == 0) {
        warp_sums[wid][0] = s0;
        warp_sums[wid][1] = s1;
        warp_sums[wid][2] = s2;
        warp_sums[wid][3] = s3;
    }
    __syncthreads();

    if (t == 0) {
        float v0 = warp_sums[0][0], v1 = warp_sums[0][1];
        float v2 = warp_sums[0][2], v3 = warp_sums[0][3];
        #pragma unroll
        for (int w = 1; w < NT / 32; w++) {
            v0 += warp_sums[w][0];
            v1 += warp_sums[w][1];
            v2 += warp_sums[w][2];
            v3 += warp_sums[w][3];
        }

        if (seg == 0) {
            slot[0] = v0; slot[1] = v1; slot[2] = v2; slot[3] = v3;
        } else {
            // ship 4 partials into rank0's slot[seg*4 .. seg*4+3]
            uint32_t local = smem_u32(&slot[seg * 4]);
            uint32_t remote;
            asm volatile("mapa.shared::cluster.u32 %0, %1, 0;"
                         : "=r"(remote) : "r"(local));
            asm volatile("st.shared::cluster.f32 [%0], %1;"
                         :: "r"(remote),      "f"(v0) : "memory");
            asm volatile("st.shared::cluster.f32 [%0], %1;"
                         :: "r"(remote + 4),  "f"(v1) : "memory");
            asm volatile("st.shared::cluster.f32 [%0], %1;"
                         :: "r"(remote + 8),  "f"(v2) : "memory");
            asm volatile("st.shared::cluster.f32 [%0], %1;"
                         :: "r"(remote + 12), "f"(v3) : "memory");
        }
    }

    // cluster barrier orders the DSMEM stores (arrive=release, wait=acquire)
    asm volatile("barrier.cluster.arrive.aligned;" ::: "memory");
    asm volatile("barrier.cluster.wait.aligned;"   ::: "memory");

    if (seg == 0 && t == 0) {
        // fixed rank-major order -> deterministic
        float o0 = slot[0] + slot[4] + slot[8]  + slot[12];
        float o1 = slot[1] + slot[5] + slot[9]  + slot[13];
        float o2 = slot[2] + slot[6] + slot[10] + slot[14];
        float o3 = slot[3] + slot[7] + slot[11] + slot[15];
        out[j0]           = o0;   // X dot 2q
        out[j0 + 1]       = o1;   // X dot 2q+1
        out[100 + j0]     = o2;   // Y dot 2q
        out[100 + j0 + 1] = o3;   // Y dot 2q+1
    }
}

extern "C" void kernel_launch(void* const* d_in, const int* in_sizes, int n_in,
                              void* d_out, int out_size)
{
    const float* X   = (const float*)d_in[0];
    const float* Y   = (const float*)d_in[1];
    const float* p   = (const float*)d_in[2];
    const int* inds1 = (const int*)d_in[3];
    const int* inds2 = (const int*)d_in[4];
    float* out       = (float*)d_out;

    quad_dot_kernel<<<NBLK, NT>>>(X, Y, p, inds1, inds2, out);
}